// round 7
// baseline (speedup 1.0000x reference)
#include <cuda_runtime.h>
#include <math.h>
#include <stdint.h>

// ---------------------------------------------------------------------------
// QuantSoftmax: B=32, C=128, H=W=80 (HW=6400). int32 input (int8 repr, zp=0),
// float32 output. Piecewise-quantized exp (qint16) + reciprocal (qint16),
// requantized to int8*OUT_SCALE.
//
// xd = -(qmax - q)*ds takes only 256 values -> exp collapses to a 256-entry
// LUT built once per launch. Main kernel: 512 threads = 4 channel-quarters
// x 128 pixels; warp = 32 consecutive pixels (full 128B coalescing on every
// LDG/STG). Each thread holds its 32 channels in registers (byte-packed,
// bias ^0x80 for per-byte SIMD max/sub); exp_q cached u16-packed in regs.
// Exp LUT replicated 32x in smem -> bank = lane -> conflict-free lookups.
// Cross-quarter max/sum via small smem arrays; 2 barriers total.
// ---------------------------------------------------------------------------

#define C_DIM 128
#define HW_DIM 6400
#define NTHREADS 512
#define PX_PER_CTA 128

__device__ float g_exp_lut[256];   // quantized exp value (integer-valued float)
__device__ float g_rtab1[256];     // recip table, region (0.1, 250)
__device__ float g_rtab2[256];     // recip table, region (250, 500)

__device__ __forceinline__ float quant_i16(float y, float scale) {
    float q = rintf(__fdiv_rn(y, scale));           // jnp.round = half-even
    return fminf(fmaxf(q, -32768.0f), 32767.0f);
}

__device__ __forceinline__ float exp_f32(float x) {
    return (float)exp((double)x);                   // ~correctly-rounded f32 exp
}

// one block, 256 threads: build LUTs
__global__ void build_luts_kernel(const float* __restrict__ ds_ptr) {
    int i = threadIdx.x;                            // 0..255
    float ds = ds_ptr[0];
    const float ESCALE = (float)(2.0 / 65535.0);
    const float RSCALE = (float)((1.0 / 0.1) * 2.0 / 65535.0);

    // ---- exp LUT over d = qmax - q in [0,255], x = -d*ds ----
    float x = __fmul_rn(-(float)i, ds);
    float y = quant_i16(exp_f32(-40.0f), ESCALE);   // left constant
    if (x >= -40.0f) {                              // line (-40,-20)
        float y0 = exp_f32(-40.0f), y1 = exp_f32(-20.0f);
        float t = __fadd_rn(y0, __fmul_rn(__fadd_rn(x, 40.0f),
                                          __fdiv_rn(__fadd_rn(y1, -y0), 20.0f)));
        y = quant_i16(t, ESCALE);
    }
    if (x >= -20.0f) {                              // table (-20,-10)
        float idxf = rintf(__fmul_rn(__fadd_rn(x, 20.0f), (float)(255.0 / 10.0)));
        idxf = fminf(fmaxf(idxf, 0.0f), 255.0f);
        float step = __fdiv_rn(10.0f, 255.0f);
        float xs = __fadd_rn(-20.0f, __fmul_rn(idxf, step));
        y = quant_i16(exp_f32(xs), ESCALE);
    }
    if (x >= -10.0f) {                              // table (-10,0)
        float idxf = rintf(__fmul_rn(__fadd_rn(x, 10.0f), (float)(255.0 / 10.0)));
        idxf = fminf(fmaxf(idxf, 0.0f), 255.0f);
        float step = __fdiv_rn(10.0f, 255.0f);
        float xs = __fadd_rn(-10.0f, __fmul_rn(idxf, step));
        y = quant_i16(exp_f32(xs), ESCALE);
    }
    if (x >= 0.0f) {                                // line (0,1): only d=0
        float y0 = exp_f32(0.0f), y1 = exp_f32(1.0f);
        float t = __fadd_rn(y0, __fmul_rn(x, __fdiv_rn(__fadd_rn(y1, -y0), 1.0f)));
        y = quant_i16(t, ESCALE);
    }
    if (x > 1.0f) y = quant_i16(exp_f32(1.0f), ESCALE);
    g_exp_lut[i] = y;

    // ---- recip tables (independent of ds) ----
    {
        float step1 = __fdiv_rn((float)(250.0 - 0.1), 255.0f);
        float xs1 = __fadd_rn(0.1f, __fmul_rn((float)i, step1));
        g_rtab1[i] = quant_i16(__fdiv_rn(1.0f, xs1), RSCALE);
        float step2 = __fdiv_rn(250.0f, 255.0f);
        float xs2 = __fadd_rn(250.0f, __fmul_rn((float)i, step2));
        g_rtab2[i] = quant_i16(__fdiv_rn(1.0f, xs2), RSCALE);
    }
}

__global__ __launch_bounds__(NTHREADS, 3)
void quant_softmax_kernel(const int* __restrict__ in, float* __restrict__ out) {
    __shared__ float slut32[256 * 32];   // 32x replicated: slut32[d*32+lane], 32 KB
    __shared__ int   smax[NTHREADS];
    __shared__ float ssum[NTHREADS];

    int tid = threadIdx.x;
    int lane = tid & 31;
    int px = tid & 127;                  // pixel within CTA's 128
    int cq = tid >> 7;                   // channel quarter 0..3

    // fill replicated LUT (consecutive -> conflict-free); barrier merged below
#pragma unroll
    for (int i = 0; i < 16; i++) {
        int j = tid + i * NTHREADS;      // 0..8191
        slut32[j] = g_exp_lut[j >> 5];
    }

    int P = blockIdx.x * PX_PER_CTA + px;    // global pixel (never straddles b)
    int b = P / HW_DIM;
    int hw = P - b * HW_DIM;

    const int* p = in + (size_t)b * C_DIM * HW_DIM + (size_t)(cq * 32) * HW_DIM + hw;

    // ---- pass 1: load 32 channels into 8 byte-packed regs (biased ^0x80) ----
    unsigned w[8];
    unsigned mx4 = 0u;                   // biased -128 = 0
#pragma unroll
    for (int k = 0; k < 8; k++) {
        int q0 = __ldcs(&p[(4 * k + 0) * HW_DIM]);
        int q1 = __ldcs(&p[(4 * k + 1) * HW_DIM]);
        int q2 = __ldcs(&p[(4 * k + 2) * HW_DIM]);
        int q3 = __ldcs(&p[(4 * k + 3) * HW_DIM]);
        unsigned t = (unsigned)(q0 & 0xFF) | ((unsigned)(q1 & 0xFF) << 8) |
                     ((unsigned)(q2 & 0xFF) << 16) | ((unsigned)q3 << 24);
        t ^= 0x80808080u;                // bias to unsigned domain
        mx4 = __vmaxu4(mx4, t);
        w[k] = t;
    }
    // horizontal max of 4 bytes (biased/unsigned)
    mx4 = __vmaxu4(mx4, mx4 >> 16);
    mx4 = __vmaxu4(mx4, mx4 >> 8);
    int mb = (int)(mx4 & 0xFF);          // biased max of this thread's 32 ch
    smax[tid] = mb;
    __syncthreads();                     // covers LUT fill + smax
    mb = max(max(smax[px], smax[px + 128]), max(smax[px + 256], smax[px + 384]));
    unsigned m4 = (unsigned)mb * 0x01010101u;   // broadcast biased max

    // ---- pass 2: d = m - q per byte, conflict-free LUT, sum; cache exp_q ----
    unsigned ew[16];
    float sum = 0.0f;
#pragma unroll
    for (int k = 0; k < 8; k++) {
        unsigned d4 = __vsub4(m4, w[k]); // per-byte, exact (m >= q)
        int a0 = (int)(d4 & 0xFF);
        int a1 = (int)((d4 >> 8) & 0xFF);
        int a2 = (int)((d4 >> 16) & 0xFF);
        int a3 = (int)(d4 >> 24);
        float e0 = slut32[a0 * 32 + lane];
        float e1 = slut32[a1 * 32 + lane];
        float e2 = slut32[a2 * 32 + lane];
        float e3 = slut32[a3 * 32 + lane];
        sum += (e0 + e1) + (e2 + e3);    // integers: thread sum < 2^20, exact
        ew[2 * k + 0] = (unsigned)(int)e0 | (((unsigned)(int)e1) << 16);
        ew[2 * k + 1] = (unsigned)(int)e2 | (((unsigned)(int)e3) << 16);
    }
    ssum[tid] = sum;
    __syncthreads();
    sum = (ssum[px] + ssum[px + 128]) + (ssum[px + 256] + ssum[px + 384]);

    // ---- reciprocal (all 4 quarter-threads compute identically) ----
    // shift = ceil(log2(128)) = 7
    float sum_sh = rintf(sum * 0.0078125f);                 // exact /128
    sum_sh = fminf(fmaxf(sum_sh, -32768.0f), 32767.0f);
    const float DIVSC = (float)(2.0 / 65535.0 * 128.0);
    float v = __fmul_rn(sum_sh, DIVSC);
    const float RSCALE = (float)((1.0 / 0.1) * 2.0 / 65535.0);

    float r = quant_i16(__fdiv_rn(1.0f, 0.001f), RSCALE);   // left const
    if (v >= 0.001f) {                                      // line (0.001,0.1)
        float y0 = __fdiv_rn(1.0f, 0.001f), y1 = __fdiv_rn(1.0f, 0.1f);
        float t = __fadd_rn(y0, __fmul_rn(__fadd_rn(v, -0.001f),
                                          __fdiv_rn(__fadd_rn(y1, -y0), (float)(0.1 - 0.001))));
        r = quant_i16(t, RSCALE);
    }
    if (v >= 0.1f) {                                        // table (0.1,250)
        float idxf = rintf(__fmul_rn(__fadd_rn(v, -0.1f), (float)(255.0 / 249.9)));
        idxf = fminf(fmaxf(idxf, 0.0f), 255.0f);
        r = g_rtab1[(int)idxf];
    }
    if (v >= 250.0f) {                                      // table (250,500)
        float idxf = rintf(__fmul_rn(__fadd_rn(v, -250.0f), (float)(255.0 / 250.0)));
        idxf = fminf(fmaxf(idxf, 0.0f), 255.0f);
        r = g_rtab2[(int)idxf];
    }
    if (v >= 500.0f) {                                      // line (500,700)
        float y0 = __fdiv_rn(1.0f, 500.0f), y1 = __fdiv_rn(1.0f, 700.0f);
        float t = __fadd_rn(y0, __fmul_rn(__fadd_rn(v, -500.0f),
                                          __fdiv_rn(__fadd_rn(y1, -y0), 200.0f)));
        r = quant_i16(t, RSCALE);
    }
    if (v > 700.0f) r = quant_i16(__fdiv_rn(1.0f, 700.0f), RSCALE);

    // ---- pass 3: out = clip(round((exp_q*recip_q)*K), i8) * OUT_SCALE ----
    const float KF = (float)((2.0 / 65535.0) * ((1.0 / 0.1) * 2.0 / 65535.0) / (2.0 / 255.0));
    const float OUTSC = (float)(2.0 / 255.0);
    float* po = out + (size_t)b * C_DIM * HW_DIM + (size_t)(cq * 32) * HW_DIM + hw;
#pragma unroll
    for (int k = 0; k < 8; k++) {
        unsigned w0 = ew[2 * k + 0];
        unsigned w1 = ew[2 * k + 1];
        float e0 = (float)(w0 & 0xFFFF);
        float e1 = (float)(w0 >> 16);
        float e2 = (float)(w1 & 0xFFFF);
        float e3 = (float)(w1 >> 16);
        float p0 = rintf(__fmul_rn(__fmul_rn(e0, r), KF));
        float p1 = rintf(__fmul_rn(__fmul_rn(e1, r), KF));
        float p2 = rintf(__fmul_rn(__fmul_rn(e2, r), KF));
        float p3 = rintf(__fmul_rn(__fmul_rn(e3, r), KF));
        p0 = fminf(fmaxf(p0, -128.0f), 127.0f);
        p1 = fminf(fmaxf(p1, -128.0f), 127.0f);
        p2 = fminf(fmaxf(p2, -128.0f), 127.0f);
        p3 = fminf(fmaxf(p3, -128.0f), 127.0f);
        __stcs(&po[(4 * k + 0) * HW_DIM], p0 * OUTSC);
        __stcs(&po[(4 * k + 1) * HW_DIM], p1 * OUTSC);
        __stcs(&po[(4 * k + 2) * HW_DIM], p2 * OUTSC);
        __stcs(&po[(4 * k + 3) * HW_DIM], p3 * OUTSC);
    }
}

extern "C" void kernel_launch(void* const* d_in, const int* in_sizes, int n_in,
                              void* d_out, int out_size) {
    const int* data = (const int*)d_in[0];
    const float* data_scale = (const float*)d_in[1];
    float* out = (float*)d_out;

    build_luts_kernel<<<1, 256>>>(data_scale);

    int total = in_sizes[0];
    int B = total / (C_DIM * HW_DIM);
    int blocks = (B * HW_DIM) / PX_PER_CTA;
    quant_softmax_kernel<<<blocks, NTHREADS>>>(data, out);
}